// round 5
// baseline (speedup 1.0000x reference)
#include <cuda_runtime.h>
#include <math.h>

// ---------------------------------------------------------------------------
// out = gelu_tanh(x) * gate(row)
// gate = exp(-tau*cos) * (1 + w*relu(tanh(sigma*mean|z|) - surp_ema))
// x [4,4096,2048] fp32 -> 16384 rows, D=2048.
// CTA: 256 threads, 8 cols/thread, 8 rows/CTA processed as 4 ROW-PAIRS.
// Channel stats in SMEM, loaded once per pair (amortized over 2 rows).
// ---------------------------------------------------------------------------

#define R_PER_CTA 8

__device__ __forceinline__ float ex2f(float v) {
    float y; asm("ex2.approx.f32 %0, %1;" : "=f"(y) : "f"(v)); return y;
}
__device__ __forceinline__ float rcpf(float v) {
    float y; asm("rcp.approx.f32 %0, %1;" : "=f"(y) : "f"(v)); return y;
}
__device__ __forceinline__ float tanhf_hw(float v) {
    float y; asm("tanh.approx.f32 %0, %1;" : "=f"(y) : "f"(v)); return y;
}
__device__ __forceinline__ float softplus_f(float v) {
    return (v > 20.0f) ? v : log1pf(expf(v));
}
__device__ __forceinline__ float warp_sum(float v) {
    #pragma unroll
    for (int o = 16; o > 0; o >>= 1)
        v += __shfl_xor_sync(0xffffffffu, v, o);
    return v;
}

// gelu = 0.5x + 0.5x * tanh(x*(C1 + C2*x^2))
__device__ __forceinline__ float gelu_hw(float x) {
    const float C1 = 0.7978845608f;   // sqrt(2/pi)
    const float C2 = 0.0356774081f;   // C1 * 0.044715
    float u = x * fmaf(x * x, C2, C1);
    float t = tanhf_hw(u);
    float h = 0.5f * x;
    return fmaf(h, t, h);
}

__global__ __launch_bounds__(256, 4)
void fused_gelu_gate(const float* __restrict__ x,
                     const float* __restrict__ ema_mean,
                     const float* __restrict__ ema_sq,
                     const float* __restrict__ ema_out,
                     const float* __restrict__ surp_ema,
                     const float* __restrict__ log_tau,
                     const float* __restrict__ log_sigma,
                     const float* __restrict__ log_w,
                     float* __restrict__ out) {
    const int D = 2048;
    const int tid = threadIdx.x;
    const int wid = tid >> 5;
    const int lid = tid & 31;
    const int i0 = tid;          // float4 index 0..255
    const int i1 = tid + 256;    // float4 index 256..511

    __shared__ float s_is[2048];
    __shared__ float s_nm[2048];
    __shared__ float s_en[2048];
    __shared__ float4 redA[8];
    __shared__ float4 redB[8];
    __shared__ float s_scal[4];   // ntau_l2e, sigma, w, surp
    __shared__ float s_gate[2];

    float4* IS4 = (float4*)s_is;
    float4* NM4 = (float4*)s_nm;
    float4* EN4 = (float4*)s_en;

    // ---- prologue: channel stats + scalars into smem ----
    {
        if (tid == 0) {
            s_scal[0] = -expf(log_tau[0]) * 1.44269504f;
            s_scal[1] = softplus_f(log_sigma[0]);
            s_scal[2] = softplus_f(log_w[0]);
            s_scal[3] = surp_ema[0];
        }
        const float4* M4 = (const float4*)ema_mean;
        const float4* Q4 = (const float4*)ema_sq;
        const float4* E4 = (const float4*)ema_out;
        float ess = 0.0f;
        #pragma unroll
        for (int c = 0; c < 2; c++) {
            int idx = (c == 0) ? i0 : i1;
            float4 m = M4[idx];
            float4 q = Q4[idx];
            float4 e = E4[idx];
            float4 isv, nmv;
            float mm[4] = {m.x, m.y, m.z, m.w};
            float qq[4] = {q.x, q.y, q.z, q.w};
            float* ip = &isv.x;
            float* np = &nmv.x;
            #pragma unroll
            for (int j = 0; j < 4; j++) {
                float var = fmaxf(qq[j] - mm[j] * mm[j], 1e-4f);
                float s = rcpf(sqrtf(var) + 1e-5f);
                ip[j] = s;
                np[j] = -mm[j] * s;
            }
            IS4[idx] = isv;
            NM4[idx] = nmv;
            EN4[idx] = e;
            ess = fmaf(e.x, e.x, ess);
            ess = fmaf(e.y, e.y, ess);
            ess = fmaf(e.z, e.z, ess);
            ess = fmaf(e.w, e.w, ess);
        }
        ess = warp_sum(ess);
        if (lid == 0) redA[wid] = make_float4(ess, 0.f, 0.f, 0.f);
        __syncthreads();
        if (wid == 0) {
            float v = redA[lid & 7].x;
            #pragma unroll
            for (int o = 4; o > 0; o >>= 1) v += __shfl_xor_sync(0xffffffffu, v, o);
            if (lid == 0) s_gate[0] = rcpf(fmaxf(sqrtf(v), 1e-12f));
        }
        __syncthreads();
        float inv_norm = s_gate[0];
        float4 e0 = EN4[i0], e1 = EN4[i1];
        e0.x *= inv_norm; e0.y *= inv_norm; e0.z *= inv_norm; e0.w *= inv_norm;
        e1.x *= inv_norm; e1.y *= inv_norm; e1.z *= inv_norm; e1.w *= inv_norm;
        EN4[i0] = e0;
        EN4[i1] = e1;
        __syncthreads();
    }

    // ---- row-pair loop ----
    long long row0 = (long long)blockIdx.x * R_PER_CTA;
    const float* xbase = x + row0 * D;
    float*       obase = out + row0 * D;

    #pragma unroll 1
    for (int p = 0; p < R_PER_CTA / 2; p++) {
        const float4* xrA = (const float4*)(xbase + (long long)(2 * p) * D);
        const float4* xrB = (const float4*)(xbase + (long long)(2 * p + 1) * D);
        float4 a0 = __ldcs(xrA + i0);
        float4 a1 = __ldcs(xrA + i1);
        float4 b0 = __ldcs(xrB + i0);
        float4 b1 = __ldcs(xrB + i1);

        float azA = 0.f, sqA = 0.f, dtA = 0.f;
        float azB = 0.f, sqB = 0.f, dtB = 0.f;

        #pragma unroll
        for (int c = 0; c < 2; c++) {
            int idx = (c == 0) ? i0 : i1;
            float4 isv = IS4[idx];
            float4 nmv = NM4[idx];
            float4 env = EN4[idx];
            float ip[4] = {isv.x, isv.y, isv.z, isv.w};
            float np[4] = {nmv.x, nmv.y, nmv.z, nmv.w};
            float ep[4] = {env.x, env.y, env.z, env.w};

            float4& va = (c == 0) ? a0 : a1;
            float4& vb = (c == 0) ? b0 : b1;
            float* pa = &va.x;
            float* pb = &vb.x;
            #pragma unroll
            for (int j = 0; j < 4; j++) {
                float xa = pa[j];
                azA += fabsf(fmaf(xa, ip[j], np[j]));
                float oa = gelu_hw(xa);
                pa[j] = oa;                       // in-place x -> gelu(x)
                sqA = fmaf(oa, oa, sqA);
                dtA = fmaf(oa, ep[j], dtA);

                float xb = pb[j];
                azB += fabsf(fmaf(xb, ip[j], np[j]));
                float ob = gelu_hw(xb);
                pb[j] = ob;
                sqB = fmaf(ob, ob, sqB);
                dtB = fmaf(ob, ep[j], dtB);
            }
        }

        azA = warp_sum(azA); sqA = warp_sum(sqA); dtA = warp_sum(dtA);
        azB = warp_sum(azB); sqB = warp_sum(sqB); dtB = warp_sum(dtB);
        if (lid == 0) {
            redA[wid] = make_float4(azA, sqA, dtA, 0.0f);
            redB[wid] = make_float4(azB, sqB, dtB, 0.0f);
        }
        __syncthreads();

        if (wid == 0) {
            float4 vA = redA[lid & 7];
            float4 vB = redB[lid & 7];
            #pragma unroll
            for (int o = 4; o > 0; o >>= 1) {
                vA.x += __shfl_xor_sync(0xffffffffu, vA.x, o);
                vA.y += __shfl_xor_sync(0xffffffffu, vA.y, o);
                vA.z += __shfl_xor_sync(0xffffffffu, vA.z, o);
                vB.x += __shfl_xor_sync(0xffffffffu, vB.x, o);
                vB.y += __shfl_xor_sync(0xffffffffu, vB.y, o);
                vB.z += __shfl_xor_sync(0xffffffffu, vB.z, o);
            }
            if (lid == 0) {
                float ntl = s_scal[0], sg = s_scal[1], w = s_scal[2], sp = s_scal[3];

                float smA = fmaxf(tanhf_hw(sg * (vA.x * (1.0f / 2048.0f))) - sp, 0.0f);
                float csA = vA.z * rsqrtf(fmaxf(vA.y, 1e-24f));
                csA = fminf(fmaxf(csA, -1.0f), 1.0f);
                s_gate[0] = ex2f(ntl * csA) * fmaf(w, smA, 1.0f);

                float smB = fmaxf(tanhf_hw(sg * (vB.x * (1.0f / 2048.0f))) - sp, 0.0f);
                float csB = vB.z * rsqrtf(fmaxf(vB.y, 1e-24f));
                csB = fminf(fmaxf(csB, -1.0f), 1.0f);
                s_gate[1] = ex2f(ntl * csB) * fmaf(w, smB, 1.0f);
            }
        }
        __syncthreads();
        float gA = s_gate[0];
        float gB = s_gate[1];

        float4* orA = (float4*)(obase + (long long)(2 * p) * D);
        float4* orB = (float4*)(obase + (long long)(2 * p + 1) * D);
        float4 oa0 = {a0.x * gA, a0.y * gA, a0.z * gA, a0.w * gA};
        float4 oa1 = {a1.x * gA, a1.y * gA, a1.z * gA, a1.w * gA};
        float4 ob0 = {b0.x * gB, b0.y * gB, b0.z * gB, b0.w * gB};
        float4 ob1 = {b1.x * gB, b1.y * gB, b1.z * gB, b1.w * gB};
        __stcs(orA + i0, oa0);
        __stcs(orA + i1, oa1);
        __stcs(orB + i0, ob0);
        __stcs(orB + i1, ob1);
    }
}

extern "C" void kernel_launch(void* const* d_in, const int* in_sizes, int n_in,
                              void* d_out, int out_size) {
    const float* x        = (const float*)d_in[0];
    const float* ema_mean = (const float*)d_in[1];
    const float* ema_sq   = (const float*)d_in[2];
    const float* ema_out  = (const float*)d_in[3];
    const float* surp_ema = (const float*)d_in[4];
    const float* log_tau  = (const float*)d_in[5];
    const float* log_sig  = (const float*)d_in[6];
    const float* log_w    = (const float*)d_in[7];
    float* out = (float*)d_out;

    int D = in_sizes[1];                       // 2048
    long long total = (long long)in_sizes[0];  // 33554432
    int rows = (int)(total / D);               // 16384
    int grid = rows / R_PER_CTA;               // 2048

    fused_gelu_gate<<<grid, 256>>>(x, ema_mean, ema_sq, ema_out, surp_ema,
                                   log_tau, log_sig, log_w, out);
}

// round 6
// speedup vs baseline: 1.0876x; 1.0876x over previous
#include <cuda_runtime.h>
#include <math.h>

// ---------------------------------------------------------------------------
// out = gelu_tanh(x) * gate(row)
// gate = exp(-tau*cos) * (1 + w*relu(tanh(sigma*mean|z|) - surp_ema))
// x [4,4096,2048] fp32 -> 16384 rows, D=2048.
// CTA: 256 threads = 4 row-TEAMS of 2 warps. Each team owns one row at a time
// (32 floats/thread in regs), syncs only within the team via named barriers.
// Channel stats in SMEM. 8 rows/CTA (2 per team), grid 2048.
// ---------------------------------------------------------------------------

#define R_PER_CTA 8
#define R_PER_TEAM 2

__device__ __forceinline__ float ex2f(float v) {
    float y; asm("ex2.approx.f32 %0, %1;" : "=f"(y) : "f"(v)); return y;
}
__device__ __forceinline__ float rcpf(float v) {
    float y; asm("rcp.approx.f32 %0, %1;" : "=f"(y) : "f"(v)); return y;
}
__device__ __forceinline__ float tanhf_hw(float v) {
    float y; asm("tanh.approx.f32 %0, %1;" : "=f"(y) : "f"(v)); return y;
}
__device__ __forceinline__ float softplus_f(float v) {
    return (v > 20.0f) ? v : log1pf(expf(v));
}
__device__ __forceinline__ float warp_sum(float v) {
    #pragma unroll
    for (int o = 16; o > 0; o >>= 1)
        v += __shfl_xor_sync(0xffffffffu, v, o);
    return v;
}
__device__ __forceinline__ void team_bar(int id) {
    asm volatile("bar.sync %0, 64;" :: "r"(id) : "memory");
}

// gelu = 0.5x + 0.5x * tanh(x*(C1 + C2*x^2))
__device__ __forceinline__ float gelu_hw(float x) {
    const float C1 = 0.7978845608f;   // sqrt(2/pi)
    const float C2 = 0.0356774081f;   // C1 * 0.044715
    float u = x * fmaf(x * x, C2, C1);
    float t = tanhf_hw(u);
    float h = 0.5f * x;
    return fmaf(h, t, h);
}

__global__ __launch_bounds__(256, 4)
void fused_gelu_gate(const float* __restrict__ x,
                     const float* __restrict__ ema_mean,
                     const float* __restrict__ ema_sq,
                     const float* __restrict__ ema_out,
                     const float* __restrict__ surp_ema,
                     const float* __restrict__ log_tau,
                     const float* __restrict__ log_sigma,
                     const float* __restrict__ log_w,
                     float* __restrict__ out) {
    const int D = 2048;
    const int tid = threadIdx.x;
    const int wid = tid >> 5;
    const int lid = tid & 31;

    __shared__ float s_is[2048];
    __shared__ float s_nm[2048];
    __shared__ float s_en[2048];
    __shared__ float4 s_pair[2][4][2];   // [parity][team][half]
    __shared__ float s_scal[4];          // ntau_l2e, sigma, w, surp

    float4* IS4 = (float4*)s_is;
    float4* NM4 = (float4*)s_nm;
    float4* EN4 = (float4*)s_en;

    // ---- prologue: channel stats + scalars into smem ----
    {
        if (tid == 0) {
            s_scal[0] = -expf(log_tau[0]) * 1.44269504f;
            s_scal[1] = softplus_f(log_sigma[0]);
            s_scal[2] = softplus_f(log_w[0]);
            s_scal[3] = surp_ema[0];
        }
        const float4* M4 = (const float4*)ema_mean;
        const float4* Q4 = (const float4*)ema_sq;
        const float4* E4 = (const float4*)ema_out;
        float ess = 0.0f;
        #pragma unroll
        for (int c = 0; c < 2; c++) {
            int idx = tid + c * 256;
            float4 m = M4[idx];
            float4 q = Q4[idx];
            float4 e = E4[idx];
            float4 isv, nmv;
            float mm[4] = {m.x, m.y, m.z, m.w};
            float qq[4] = {q.x, q.y, q.z, q.w};
            float* ip = &isv.x;
            float* np = &nmv.x;
            #pragma unroll
            for (int j = 0; j < 4; j++) {
                float var = fmaxf(qq[j] - mm[j] * mm[j], 1e-4f);
                float s = rcpf(sqrtf(var) + 1e-5f);
                ip[j] = s;
                np[j] = -mm[j] * s;
            }
            IS4[idx] = isv;
            NM4[idx] = nmv;
            EN4[idx] = e;
            ess = fmaf(e.x, e.x, ess);
            ess = fmaf(e.y, e.y, ess);
            ess = fmaf(e.z, e.z, ess);
            ess = fmaf(e.w, e.w, ess);
        }
        ess = warp_sum(ess);
        if (lid == 0) s_pair[0][wid >> 1][wid & 1] = make_float4(ess, 0.f, 0.f, 0.f);
        __syncthreads();
        if (wid == 0) {
            float v = (&s_pair[0][0][0].x)[(lid & 7) * 4];
            #pragma unroll
            for (int o = 4; o > 0; o >>= 1) v += __shfl_xor_sync(0xffffffffu, v, o);
            if (lid == 0) s_pair[1][0][0].x = rcpf(fmaxf(sqrtf(v), 1e-12f));
        }
        __syncthreads();
        float inv_norm = s_pair[1][0][0].x;
        #pragma unroll
        for (int c = 0; c < 2; c++) {
            int idx = tid + c * 256;
            float4 e = EN4[idx];
            e.x *= inv_norm; e.y *= inv_norm; e.z *= inv_norm; e.w *= inv_norm;
            EN4[idx] = e;
        }
        __syncthreads();
    }

    const float ntl = s_scal[0];
    const float sg  = s_scal[1];
    const float w   = s_scal[2];
    const float sp  = s_scal[3];

    const int team = wid >> 1;      // 0..3
    const int half = wid & 1;       // 0..1
    const int ib   = half * 256 + lid;   // float4 base index in row

    long long row0 = (long long)blockIdx.x * R_PER_CTA;
    const float4* xbase4 = (const float4*)(x + row0 * D);
    float4*       obase4 = (float4*)(out + row0 * D);

    #pragma unroll 1
    for (int it = 0; it < R_PER_TEAM; it++) {
        const int r = team * R_PER_TEAM + it;
        const float4* xr = xbase4 + (long long)r * 512;

        // 8 back-to-back LDG.128
        float4 v[8];
        #pragma unroll
        for (int k = 0; k < 8; k++) v[k] = __ldcs(xr + ib + k * 32);

        float az = 0.f, sq = 0.f, dt = 0.f;
        #pragma unroll
        for (int k = 0; k < 8; k++) {
            int idx = ib + k * 32;
            float4 isv = IS4[idx];
            float4 nmv = NM4[idx];
            float4 env = EN4[idx];
            float* pv = &v[k].x;
            float ip[4] = {isv.x, isv.y, isv.z, isv.w};
            float np[4] = {nmv.x, nmv.y, nmv.z, nmv.w};
            float ep[4] = {env.x, env.y, env.z, env.w};
            #pragma unroll
            for (int j = 0; j < 4; j++) {
                float xj = pv[j];
                az += fabsf(fmaf(xj, ip[j], np[j]));
                float o = gelu_hw(xj);
                pv[j] = o;                   // in-place x -> gelu(x)
                sq = fmaf(o, o, sq);
                dt = fmaf(o, ep[j], dt);
            }
        }

        az = warp_sum(az);
        sq = warp_sum(sq);
        dt = warp_sum(dt);
        if (lid == 0) s_pair[it & 1][team][half] = make_float4(az, sq, dt, 0.f);
        team_bar(team + 1);

        float4 A = s_pair[it & 1][team][0];
        float4 B = s_pair[it & 1][team][1];
        float a = A.x + B.x;
        float b = A.y + B.y;
        float c = A.z + B.z;

        float surp_mod = fmaxf(tanhf_hw(sg * (a * (1.0f / 2048.0f))) - sp, 0.0f);
        float cs = c * rsqrtf(fmaxf(b, 1e-24f));
        cs = fminf(fmaxf(cs, -1.0f), 1.0f);
        float gate = ex2f(ntl * cs) * fmaf(w, surp_mod, 1.0f);

        float4* orow = obase4 + (long long)r * 512;
        #pragma unroll
        for (int k = 0; k < 8; k++) {
            float4 o = v[k];
            o.x *= gate; o.y *= gate; o.z *= gate; o.w *= gate;
            __stcs(orow + ib + k * 32, o);
        }
    }
}

extern "C" void kernel_launch(void* const* d_in, const int* in_sizes, int n_in,
                              void* d_out, int out_size) {
    const float* x        = (const float*)d_in[0];
    const float* ema_mean = (const float*)d_in[1];
    const float* ema_sq   = (const float*)d_in[2];
    const float* ema_out  = (const float*)d_in[3];
    const float* surp_ema = (const float*)d_in[4];
    const float* log_tau  = (const float*)d_in[5];
    const float* log_sig  = (const float*)d_in[6];
    const float* log_w    = (const float*)d_in[7];
    float* out = (float*)d_out;

    int D = in_sizes[1];                       // 2048
    long long total = (long long)in_sizes[0];  // 33554432
    int rows = (int)(total / D);               // 16384
    int grid = rows / R_PER_CTA;               // 2048

    fused_gelu_gate<<<grid, 256>>>(x, ema_mean, ema_sq, ema_out, surp_ema,
                                   log_tau, log_sig, log_w, out);
}